// round 6
// baseline (speedup 1.0000x reference)
#include <cuda_runtime.h>

#define BB   512
#define TM1  99
#define NF   128
#define HH   256
#define Z2W  100              // padded s-width for float4 stores
#define WOFF (BB*TM1*NF)      // offset of input_encoded in out

// ---------------- device scratch (no allocations allowed) ----------------
__device__ float  g_z2[BB*NF*Z2W];        // ~26 MB, layout [b][n][s(padded 100)]
__device__ float  g_h[2][BB*HH];          // ping-pong hidden
__device__ float  g_c[2][BB*HH];          // ping-pong cell
__device__ float4 g_Wt4[384*256];         // [k][j] -> (Wi,Wf,Wg,Wo) row j, col k
__device__ float  g_W2t[TM1*Z2W];         // W2 transposed [t][s], zero-padded s=99
__device__ float  g_bias[1024];           // b_ih + b_hh

// ---------------- fast math helpers (approx err ~2^-22, safe for 1e-3) ---
__device__ __forceinline__ float ex2f(float x){ float y; asm("ex2.approx.f32 %0, %1;" : "=f"(y) : "f"(x)); return y; }
__device__ __forceinline__ float rcpf(float x){ float y; asm("rcp.approx.f32 %0, %1;" : "=f"(y) : "f"(x)); return y; }
__device__ __forceinline__ float tanh_f(float x){
    float a  = fabsf(x);
    float em = ex2f(a * -2.8853900817779268f);      // e^{-2a}
    float r  = (1.0f - em) * rcpf(1.0f + em);
    return copysignf(r, x);
}
__device__ __forceinline__ float sigm_f(float x){
    float e = ex2f(x * -1.4426950408889634f);       // e^{-x}
    return rcpf(1.0f + e);
}
__device__ __forceinline__ float wsum(float v){
    #pragma unroll
    for (int o = 16; o; o >>= 1) v += __shfl_xor_sync(0xffffffffu, v, o);
    return v;
}
__device__ __forceinline__ float wmax(float v){
    #pragma unroll
    for (int o = 16; o; o >>= 1) v = fmaxf(v, __shfl_xor_sync(0xffffffffu, v, o));
    return v;
}

// ---------------- prep: transpose/fuse weights, zero initial state --------
__global__ void prep_kernel(const float* __restrict__ W_ih, const float* __restrict__ W_hh,
                            const float* __restrict__ b_ih, const float* __restrict__ b_hh,
                            const float* __restrict__ W2)
{
    int stride = gridDim.x * blockDim.x;
    int tid0   = blockIdx.x * blockDim.x + threadIdx.x;

    // interleaved transposed LSTM weights: g_Wt4[k*256 + j] = (row j, row 256+j, 512+j, 768+j) at col k
    for (int idx = tid0; idx < 384*256; idx += stride) {
        int k = idx >> 8, j = idx & 255;
        float4 v;
        if (k < 128) {
            v.x = W_ih[(j      )*128 + k];
            v.y = W_ih[(j + 256)*128 + k];
            v.z = W_ih[(j + 512)*128 + k];
            v.w = W_ih[(j + 768)*128 + k];
        } else {
            int kk = k - 128;
            v.x = W_hh[(j      )*256 + kk];
            v.y = W_hh[(j + 256)*256 + kk];
            v.z = W_hh[(j + 512)*256 + kk];
            v.w = W_hh[(j + 768)*256 + kk];
        }
        g_Wt4[idx] = v;
    }
    // W2 transposed + zero pad
    for (int idx = tid0; idx < TM1*Z2W; idx += stride) {
        int t = idx / Z2W, s = idx - t*Z2W;
        g_W2t[idx] = (s < TM1) ? W2[s*TM1 + t] : 0.0f;
    }
    // fused bias
    for (int idx = tid0; idx < 1024; idx += stride)
        g_bias[idx] = b_ih[idx] + b_hh[idx];
    // zero initial h, c (buffer 0)
    for (int idx = tid0; idx < BB*HH; idx += stride) {
        g_h[0][idx] = 0.0f;
        g_c[0][idx] = 0.0f;
    }
}

// ---------------- z2 precompute: z2[b][n][s] = sum_t in[b,t,n]*W2[s,t]+b2[s]
// grid: 1024 blocks = (b, n-half), 256 threads
__global__ void z2_kernel(const float* __restrict__ in, const float* __restrict__ b2)
{
    __shared__ float inT[64*TM1];    // [nn][t]
    int b  = blockIdx.x >> 1;
    int nh = blockIdx.x & 1;
    int tid = threadIdx.x;

    for (int i = tid; i < 64*TM1; i += 256) {
        int t = i >> 6, nn = i & 63;
        inT[nn*TM1 + t] = in[b*TM1*NF + t*NF + nh*64 + nn];
    }
    __syncthreads();

    int w = tid >> 5, l = tid & 31;
    if (l < 25) {
        int s0 = 4*l;
        float4 bb;
        bb.x = (s0+0 < TM1) ? b2[s0+0] : 0.0f;
        bb.y = (s0+1 < TM1) ? b2[s0+1] : 0.0f;
        bb.z = (s0+2 < TM1) ? b2[s0+2] : 0.0f;
        bb.w = (s0+3 < TM1) ? b2[s0+3] : 0.0f;
        const float4* wrow = (const float4*)g_W2t;   // [t][25 float4]
        for (int nn = w*8; nn < w*8 + 8; nn++) {
            float4 acc = make_float4(0.f,0.f,0.f,0.f);
            #pragma unroll 3
            for (int t = 0; t < TM1; t++) {
                float  xv = inT[nn*TM1 + t];
                float4 wv = wrow[t*25 + l];
                acc.x = fmaf(xv, wv.x, acc.x);
                acc.y = fmaf(xv, wv.y, acc.y);
                acc.z = fmaf(xv, wv.z, acc.z);
                acc.w = fmaf(xv, wv.w, acc.w);
            }
            acc.x += bb.x; acc.y += bb.y; acc.z += bb.z; acc.w += bb.w;
            int n = nh*64 + nn;
            *(float4*)&g_z2[(b*NF + n)*Z2W + s0] = acc;
        }
    }
}

// ---------------- attention kernel (per step): z1 -> e -> softmax -> w ----
// grid: 128 blocks x 4 batches, 256 threads (8 warps)
__global__ void attn_kernel(int t, const float* __restrict__ in,
                            const float* __restrict__ W1, const float* __restrict__ b1,
                            const float* __restrict__ W3, const float* __restrict__ b3,
                            float* __restrict__ out)
{
    __shared__ float hc[4*512];      // [bi][512] = [h(256); c(256)]
    __shared__ float z1s[4*128];
    __shared__ float es[4*128];

    int tid = threadIdx.x, w = tid >> 5, l = tid & 31;
    int b0  = blockIdx.x * 4;
    const float* hsrc = g_h[t & 1];
    const float* csrc = g_c[t & 1];

    for (int i = tid; i < 4*512; i += 256) {
        int bi = i >> 9, j = i & 511;
        hc[i] = (j < 256) ? hsrc[(b0+bi)*HH + j] : csrc[(b0+bi)*HH + (j-256)];
    }
    __syncthreads();

    // hoist this lane's hc slice into registers (fixed across s)
    float4 hr[4][4];
    #pragma unroll
    for (int bi = 0; bi < 4; bi++) {
        const float4* h4 = (const float4*)(hc + bi*512);
        #pragma unroll
        for (int u = 0; u < 4; u++) hr[bi][u] = h4[l + 32*u];
    }

    // stage 1: z1[bi][s] = dot(hc[bi], W1[s]) + b1[s]
    for (int s = w; s < TM1; s += 8) {
        const float4* wr = (const float4*)(W1 + s*512);
        float4 w0 = wr[l], w1 = wr[l+32], w2 = wr[l+64], w3v = wr[l+96];
        float bv = b1[s];
        #pragma unroll
        for (int bi = 0; bi < 4; bi++) {
            float a = 0.0f;
            a = fmaf(w0.x, hr[bi][0].x, a); a = fmaf(w0.y, hr[bi][0].y, a);
            a = fmaf(w0.z, hr[bi][0].z, a); a = fmaf(w0.w, hr[bi][0].w, a);
            a = fmaf(w1.x, hr[bi][1].x, a); a = fmaf(w1.y, hr[bi][1].y, a);
            a = fmaf(w1.z, hr[bi][1].z, a); a = fmaf(w1.w, hr[bi][1].w, a);
            a = fmaf(w2.x, hr[bi][2].x, a); a = fmaf(w2.y, hr[bi][2].y, a);
            a = fmaf(w2.z, hr[bi][2].z, a); a = fmaf(w2.w, hr[bi][2].w, a);
            a = fmaf(w3v.x, hr[bi][3].x, a); a = fmaf(w3v.y, hr[bi][3].y, a);
            a = fmaf(w3v.z, hr[bi][3].z, a); a = fmaf(w3v.w, hr[bi][3].w, a);
            a = wsum(a);
            if (l == 0) z1s[bi*128 + s] = a + bv;
        }
    }
    __syncthreads();

    // stage 2: e[bi][n] = sum_s W3[s]*tanh(z1[s] + z2[b,n,s]) + b3
    for (int idx = w; idx < 512; idx += 8) {
        int bi = idx >> 7, n = idx & 127;
        const float* zrow = g_z2 + ((b0+bi)*NF + n)*Z2W;
        const float* z1r  = z1s + bi*128;
        float acc = 0.0f;
        int s;
        s = l;      acc = fmaf(W3[s], tanh_f(z1r[s] + zrow[s]), acc);
        s = l + 32; acc = fmaf(W3[s], tanh_f(z1r[s] + zrow[s]), acc);
        s = l + 64; acc = fmaf(W3[s], tanh_f(z1r[s] + zrow[s]), acc);
        if (l < 3) { s = l + 96; acc = fmaf(W3[s], tanh_f(z1r[s] + zrow[s]), acc); }
        acc = wsum(acc);
        if (l == 0) es[bi*128 + n] = acc + b3[0];
    }
    __syncthreads();

    // stage 3: softmax over n, w = attn * x_t, store input_weighted
    if (w < 4) {
        int bi = w, b = b0 + bi;
        float v0 = es[bi*128 + l],      v1 = es[bi*128 + 32 + l];
        float v2 = es[bi*128 + 64 + l], v3 = es[bi*128 + 96 + l];
        float m = fmaxf(fmaxf(v0, v1), fmaxf(v2, v3));
        m = wmax(m);
        float e0 = ex2f((v0 - m) * 1.4426950408889634f);
        float e1 = ex2f((v1 - m) * 1.4426950408889634f);
        float e2 = ex2f((v2 - m) * 1.4426950408889634f);
        float e3 = ex2f((v3 - m) * 1.4426950408889634f);
        float sum = wsum(e0 + e1 + e2 + e3);
        float r = rcpf(sum);
        const float* xrow = in  + b*TM1*NF + t*NF;
        float*       orow = out + b*TM1*NF + t*NF;
        orow[l     ] = e0 * r * xrow[l     ];
        orow[l + 32] = e1 * r * xrow[l + 32];
        orow[l + 64] = e2 * r * xrow[l + 64];
        orow[l + 96] = e3 * r * xrow[l + 96];
    }
}

// ---------------- LSTM kernel (per step): gates GEMM + cell update --------
// grid: 128 blocks = 32 batch-tiles(16) x 4 hidden-tiles(64), 256 threads
__global__ void lstm_kernel(int t, float* __restrict__ out)
{
    __shared__ float xs[16*384];     // [bb][k] : k<128 -> w, k>=128 -> h
    int tid   = threadIdx.x;
    int btile = blockIdx.x & 31;
    int htile = blockIdx.x >> 5;

    const float* hsrc = g_h[t & 1];
    const float* csrc = g_c[t & 1];
    float*       hdst = g_h[(t + 1) & 1];
    float*       cdst = g_c[(t + 1) & 1];

    for (int i = tid; i < 16*384; i += 256) {
        int bb = i / 384, k = i - bb*384;
        int b  = btile*16 + bb;
        float v = (k < 128) ? out[b*TM1*NF + t*NF + k] : hsrc[b*HH + (k - 128)];
        xs[bb*384 + k] = v;
    }
    __syncthreads();

    int hu = tid & 63, bg = tid >> 6;
    int j  = htile*64 + hu;

    float bI = g_bias[j], bF = g_bias[256 + j], bG = g_bias[512 + j], bO = g_bias[768 + j];
    float aI[4] = {bI, bI, bI, bI};
    float aF[4] = {bF, bF, bF, bF};
    float aG[4] = {bG, bG, bG, bG};
    float aO[4] = {bO, bO, bO, bO};

    const float* x0 = xs + (bg*4 + 0)*384;
    const float* x1 = xs + (bg*4 + 1)*384;
    const float* x2 = xs + (bg*4 + 2)*384;
    const float* x3 = xs + (bg*4 + 3)*384;

    #pragma unroll 4
    for (int k = 0; k < 384; k++) {
        float4 wv = g_Wt4[k*256 + j];
        float xv0 = x0[k], xv1 = x1[k], xv2 = x2[k], xv3 = x3[k];
        aI[0] = fmaf(wv.x, xv0, aI[0]); aI[1] = fmaf(wv.x, xv1, aI[1]);
        aI[2] = fmaf(wv.x, xv2, aI[2]); aI[3] = fmaf(wv.x, xv3, aI[3]);
        aF[0] = fmaf(wv.y, xv0, aF[0]); aF[1] = fmaf(wv.y, xv1, aF[1]);
        aF[2] = fmaf(wv.y, xv2, aF[2]); aF[3] = fmaf(wv.y, xv3, aF[3]);
        aG[0] = fmaf(wv.z, xv0, aG[0]); aG[1] = fmaf(wv.z, xv1, aG[1]);
        aG[2] = fmaf(wv.z, xv2, aG[2]); aG[3] = fmaf(wv.z, xv3, aG[3]);
        aO[0] = fmaf(wv.w, xv0, aO[0]); aO[1] = fmaf(wv.w, xv1, aO[1]);
        aO[2] = fmaf(wv.w, xv2, aO[2]); aO[3] = fmaf(wv.w, xv3, aO[3]);
    }

    #pragma unroll
    for (int m = 0; m < 4; m++) {
        int b = btile*16 + bg*4 + m;
        float iv = sigm_f(aI[m]);
        float fv = sigm_f(aF[m]);
        float gv = tanh_f(aG[m]);
        float ov = sigm_f(aO[m]);
        float cold = csrc[b*HH + j];
        float cn = fmaf(fv, cold, iv * gv);
        float hn = ov * tanh_f(cn);
        cdst[b*HH + j] = cn;
        hdst[b*HH + j] = hn;
        out[WOFF + b*TM1*HH + t*HH + j] = hn;
    }
}

// ---------------- launch ---------------------------------------------------
extern "C" void kernel_launch(void* const* d_in, const int* in_sizes, int n_in,
                              void* d_out, int out_size)
{
    const float* in   = (const float*)d_in[0];
    const float* W1   = (const float*)d_in[1];
    const float* b1   = (const float*)d_in[2];
    const float* W2   = (const float*)d_in[3];
    const float* b2   = (const float*)d_in[4];
    const float* W3   = (const float*)d_in[5];
    const float* b3   = (const float*)d_in[6];
    const float* W_ih = (const float*)d_in[7];
    const float* W_hh = (const float*)d_in[8];
    const float* b_ih = (const float*)d_in[9];
    const float* b_hh = (const float*)d_in[10];
    float* out = (float*)d_out;

    prep_kernel<<<148, 256>>>(W_ih, W_hh, b_ih, b_hh, W2);
    z2_kernel<<<1024, 256>>>(in, b2);
    for (int t = 0; t < TM1; t++) {
        attn_kernel<<<128, 256>>>(t, in, W1, b1, W3, b3, out);
        lstm_kernel<<<128, 256>>>(t, out);
    }
}

// round 7
// speedup vs baseline: 1.5208x; 1.5208x over previous
#include <cuda_runtime.h>

#define BB   512
#define TM1  99
#define NF   128
#define HH   256
#define Z2W  100
#define WOFF (BB*TM1*NF)
#define NBLK 128

typedef unsigned long long ull;

// ---------------- device scratch ----------------
__device__ float  g_z2[BB*NF*Z2W];        // [b][n][s(pad 100)]
__device__ float  g_h[2][BB*HH];
__device__ float  g_c[2][BB*HH];
__device__ float4 g_Wt4[384*256];         // [k][j] -> (Wi,Wf,Wg,Wo)
__device__ float  g_W2t[TM1*Z2W];
__device__ float  g_bias[1024];
__device__ volatile unsigned g_arrive[NBLK];
__device__ volatile unsigned g_release;

// ---------------- math helpers ----------------
__device__ __forceinline__ float ex2f(float x){ float y; asm("ex2.approx.f32 %0, %1;" : "=f"(y) : "f"(x)); return y; }
__device__ __forceinline__ float rcpf(float x){ float y; asm("rcp.approx.f32 %0, %1;" : "=f"(y) : "f"(x)); return y; }
__device__ __forceinline__ float tanha(float x){ float y; asm("tanh.approx.f32 %0, %1;" : "=f"(y) : "f"(x)); return y; }
__device__ __forceinline__ float tanh_f(float x){
    float a  = fabsf(x);
    float em = ex2f(a * -2.8853900817779268f);
    float r  = (1.0f - em) * rcpf(1.0f + em);
    return copysignf(r, x);
}
__device__ __forceinline__ float sigm_f(float x){
    float e = ex2f(x * -1.4426950408889634f);
    return rcpf(1.0f + e);
}
__device__ __forceinline__ float wsum(float v){
    #pragma unroll
    for (int o = 16; o; o >>= 1) v += __shfl_xor_sync(0xffffffffu, v, o);
    return v;
}
__device__ __forceinline__ float wmax(float v){
    #pragma unroll
    for (int o = 16; o; o >>= 1) v = fmaxf(v, __shfl_xor_sync(0xffffffffu, v, o));
    return v;
}
__device__ __forceinline__ ull pack2(float a, float b){ ull r; asm("mov.b64 %0, {%1,%2};" : "=l"(r) : "f"(a), "f"(b)); return r; }
__device__ __forceinline__ float2 unpack2(ull v){ float2 r; asm("mov.b64 {%0,%1}, %2;" : "=f"(r.x), "=f"(r.y) : "l"(v)); return r; }
#define FFMA2(d,a,b) asm("fma.rn.f32x2 %0, %1, %2, %0;" : "+l"(d) : "l"(a), "l"(b))

// ---------------- grid barrier (all NBLK CTAs co-resident) ----------------
__device__ __forceinline__ void gbar(int bid, unsigned k){
    __threadfence();                         // make my global writes visible
    __syncthreads();
    if (threadIdx.x == 0) g_arrive[bid] = k;
    if (bid == 0 && threadIdx.x < 32) {
        for (int i = threadIdx.x; i < NBLK; i += 32)
            while (g_arrive[i] < k) __nanosleep(20);
        __syncwarp();
        if (threadIdx.x == 0) g_release = k;
    }
    if (threadIdx.x == 0) {
        while (g_release < k) __nanosleep(20);
        __threadfence();                     // CCTL.IVALL: drop stale L1 lines
    }
    __syncthreads();
}

// ---------------- prep ----------------
__global__ void prep_kernel(const float* __restrict__ W_ih, const float* __restrict__ W_hh,
                            const float* __restrict__ b_ih, const float* __restrict__ b_hh,
                            const float* __restrict__ W2)
{
    int stride = gridDim.x * blockDim.x;
    int tid0   = blockIdx.x * blockDim.x + threadIdx.x;

    for (int idx = tid0; idx < 384*256; idx += stride) {
        int k = idx >> 8, j = idx & 255;
        float4 v;
        if (k < 128) {
            v.x = W_ih[(j      )*128 + k];
            v.y = W_ih[(j + 256)*128 + k];
            v.z = W_ih[(j + 512)*128 + k];
            v.w = W_ih[(j + 768)*128 + k];
        } else {
            int kk = k - 128;
            v.x = W_hh[(j      )*256 + kk];
            v.y = W_hh[(j + 256)*256 + kk];
            v.z = W_hh[(j + 512)*256 + kk];
            v.w = W_hh[(j + 768)*256 + kk];
        }
        g_Wt4[idx] = v;
    }
    for (int idx = tid0; idx < TM1*Z2W; idx += stride) {
        int t = idx / Z2W, s = idx - t*Z2W;
        g_W2t[idx] = (s < TM1) ? W2[s*TM1 + t] : 0.0f;
    }
    for (int idx = tid0; idx < 1024; idx += stride)
        g_bias[idx] = b_ih[idx] + b_hh[idx];
    for (int idx = tid0; idx < BB*HH; idx += stride) {
        g_h[0][idx] = 0.0f;
        g_c[0][idx] = 0.0f;
    }
    if (blockIdx.x == 0) {
        if (threadIdx.x < NBLK) g_arrive[threadIdx.x] = 0;
        if (threadIdx.x == 0)   g_release = 0;
    }
}

// ---------------- z2 precompute ----------------
__global__ void z2_kernel(const float* __restrict__ in, const float* __restrict__ b2)
{
    __shared__ float inT[64*TM1];
    int b  = blockIdx.x >> 1;
    int nh = blockIdx.x & 1;
    int tid = threadIdx.x;

    for (int i = tid; i < 64*TM1; i += 256) {
        int t = i >> 6, nn = i & 63;
        inT[nn*TM1 + t] = in[b*TM1*NF + t*NF + nh*64 + nn];
    }
    __syncthreads();

    int w = tid >> 5, l = tid & 31;
    if (l < 25) {
        int s0 = 4*l;
        float4 bb;
        bb.x = (s0+0 < TM1) ? b2[s0+0] : 0.0f;
        bb.y = (s0+1 < TM1) ? b2[s0+1] : 0.0f;
        bb.z = (s0+2 < TM1) ? b2[s0+2] : 0.0f;
        bb.w = (s0+3 < TM1) ? b2[s0+3] : 0.0f;
        const float4* wrow = (const float4*)g_W2t;
        for (int nn = w*8; nn < w*8 + 8; nn++) {
            float4 acc = make_float4(0.f,0.f,0.f,0.f);
            #pragma unroll 3
            for (int t = 0; t < TM1; t++) {
                float  xv = inT[nn*TM1 + t];
                float4 wv = wrow[t*25 + l];
                acc.x = fmaf(xv, wv.x, acc.x);
                acc.y = fmaf(xv, wv.y, acc.y);
                acc.z = fmaf(xv, wv.z, acc.z);
                acc.w = fmaf(xv, wv.w, acc.w);
            }
            acc.x += bb.x; acc.y += bb.y; acc.z += bb.z; acc.w += bb.w;
            int n = nh*64 + nn;
            *(float4*)&g_z2[(b*NF + n)*Z2W + s0] = acc;
        }
    }
}

// ---------------- persistent fused kernel ----------------
// grid = 128 x 256. dyn smem: wsmu 98304B | xs (64x386f) 98816B | attn 12288B
#define SMEM_PERSIST (52352*4)
__global__ __launch_bounds__(256, 1) void persist_kernel(
    const float* __restrict__ in, const float* __restrict__ W1, const float* __restrict__ b1,
    const float* __restrict__ W3, const float* __restrict__ b3, float* __restrict__ out)
{
    extern __shared__ float sm[];
    ull*   wsmu = (ull*)sm;                  // [gate][kp][q] : (w[2kp],w[2kp+1])
    float* xsf  = sm + 24576;                // [bb][k], row stride 386
    float* hc   = sm + 49280;                // 4*512
    float* z1s  = sm + 51328;                // 4*128
    float* es   = sm + 51840;                // 4*128

    int bid = blockIdx.x, tid = threadIdx.x;
    int wrp = tid >> 5, l = tid & 31;
    int jt  = bid >> 3, bt = bid & 7;        // 16 j-tiles x 8 b-tiles

    // stage weight slice into smem once
    for (int idx = tid; idx < 192*16; idx += 256) {
        int kp = idx >> 4, q2 = idx & 15;
        int j  = jt*16 + q2;
        float4 w0 = g_Wt4[(2*kp  )*256 + j];
        float4 w1 = g_Wt4[(2*kp+1)*256 + j];
        wsmu[(0*192 + kp)*16 + q2] = pack2(w0.x, w1.x);
        wsmu[(1*192 + kp)*16 + q2] = pack2(w0.y, w1.y);
        wsmu[(2*192 + kp)*16 + q2] = pack2(w0.z, w1.z);
        wsmu[(3*192 + kp)*16 + q2] = pack2(w0.w, w1.w);
    }

    int q  = tid & 15, bg = tid >> 4;        // GEMM mapping
    int jj = jt*16 + q;
    float bI = g_bias[jj], bF = g_bias[256+jj], bG = g_bias[512+jj], bO = g_bias[768+jj];
    float creg[4] = {0.f, 0.f, 0.f, 0.f};
    __syncthreads();

    unsigned bar = 0;
    for (int t = 0; t < TM1; t++) {
        const float* hsrc = g_h[t & 1];
        const float* csrc = g_c[t & 1];

        // ============ ATTENTION (batches bid*4 .. +3) ============
        {
            int b0 = bid * 4;
            for (int i = tid; i < 4*512; i += 256) {
                int bi = i >> 9, j = i & 511;
                hc[i] = (j < 256) ? hsrc[(b0+bi)*HH + j] : csrc[(b0+bi)*HH + (j-256)];
            }
            __syncthreads();

            float4 hr[4][4];
            #pragma unroll
            for (int bi = 0; bi < 4; bi++) {
                const float4* h4 = (const float4*)(hc + bi*512);
                #pragma unroll
                for (int u = 0; u < 4; u++) hr[bi][u] = h4[l + 32*u];
            }

            for (int s = wrp; s < TM1; s += 8) {
                const float4* wr = (const float4*)(W1 + s*512);
                float4 w0 = wr[l], w1v = wr[l+32], w2v = wr[l+64], w3v = wr[l+96];
                float bv = b1[s];
                #pragma unroll
                for (int bi = 0; bi < 4; bi++) {
                    float a = 0.0f;
                    a = fmaf(w0.x, hr[bi][0].x, a);  a = fmaf(w0.y, hr[bi][0].y, a);
                    a = fmaf(w0.z, hr[bi][0].z, a);  a = fmaf(w0.w, hr[bi][0].w, a);
                    a = fmaf(w1v.x, hr[bi][1].x, a); a = fmaf(w1v.y, hr[bi][1].y, a);
                    a = fmaf(w1v.z, hr[bi][1].z, a); a = fmaf(w1v.w, hr[bi][1].w, a);
                    a = fmaf(w2v.x, hr[bi][2].x, a); a = fmaf(w2v.y, hr[bi][2].y, a);
                    a = fmaf(w2v.z, hr[bi][2].z, a); a = fmaf(w2v.w, hr[bi][2].w, a);
                    a = fmaf(w3v.x, hr[bi][3].x, a); a = fmaf(w3v.y, hr[bi][3].y, a);
                    a = fmaf(w3v.z, hr[bi][3].z, a); a = fmaf(w3v.w, hr[bi][3].w, a);
                    a = wsum(a);
                    if (l == 0) z1s[bi*128 + s] = a + bv;
                }
            }
            __syncthreads();

            for (int idx = wrp; idx < 512; idx += 8) {
                int bi = idx >> 7, n = idx & 127;
                const float* zrow = g_z2 + ((size_t)(b0+bi)*NF + n)*Z2W;
                const float* z1r  = z1s + bi*128;
                float acc = 0.0f;
                int s;
                s = l;      acc = fmaf(W3[s], tanha(z1r[s] + zrow[s]), acc);
                s = l + 32; acc = fmaf(W3[s], tanha(z1r[s] + zrow[s]), acc);
                s = l + 64; acc = fmaf(W3[s], tanha(z1r[s] + zrow[s]), acc);
                if (l < 3) { s = l + 96; acc = fmaf(W3[s], tanha(z1r[s] + zrow[s]), acc); }
                acc = wsum(acc);
                if (l == 0) es[bi*128 + n] = acc + b3[0];
            }
            __syncthreads();

            if (wrp < 4) {
                int bi = wrp, b = b0 + bi;
                float v0 = es[bi*128 + l],      v1 = es[bi*128 + 32 + l];
                float v2 = es[bi*128 + 64 + l], v3 = es[bi*128 + 96 + l];
                float m = wmax(fmaxf(fmaxf(v0, v1), fmaxf(v2, v3)));
                float e0 = ex2f((v0 - m) * 1.4426950408889634f);
                float e1 = ex2f((v1 - m) * 1.4426950408889634f);
                float e2 = ex2f((v2 - m) * 1.4426950408889634f);
                float e3 = ex2f((v3 - m) * 1.4426950408889634f);
                float r = rcpf(wsum(e0 + e1 + e2 + e3));
                const float* xrow = in  + (size_t)b*TM1*NF + t*NF;
                float*       orow = out + (size_t)b*TM1*NF + t*NF;
                orow[l     ] = e0 * r * xrow[l     ];
                orow[l + 32] = e1 * r * xrow[l + 32];
                orow[l + 64] = e2 * r * xrow[l + 64];
                orow[l + 96] = e3 * r * xrow[l + 96];
            }
        }
        gbar(bid, ++bar);   // w(t) visible everywhere; h/c reads done

        // ============ LSTM GEMM + cell (64 batches x 16 j) ============
        {
            for (int i = tid; i < 64*384; i += 256) {
                int bb = i / 384, k = i - bb*384;
                int b  = bt*64 + bb;
                float v = (k < NF) ? out[(size_t)b*TM1*NF + t*NF + k]
                                   : hsrc[b*HH + (k - NF)];
                xsf[bb*386 + k] = v;
            }
            __syncthreads();

            const ull* xu = (const ull*)xsf;
            const ull* x0 = xu + (bg*4 + 0)*193;
            const ull* x1 = xu + (bg*4 + 1)*193;
            const ull* x2 = xu + (bg*4 + 2)*193;
            const ull* x3 = xu + (bg*4 + 3)*193;
            const ull* wI = wsmu + (0*192)*16 + q;
            const ull* wF = wsmu + (1*192)*16 + q;
            const ull* wG = wsmu + (2*192)*16 + q;
            const ull* wO = wsmu + (3*192)*16 + q;

            ull aI[4] = {0,0,0,0}, aF[4] = {0,0,0,0}, aG[4] = {0,0,0,0}, aO[4] = {0,0,0,0};

            #pragma unroll 2
            for (int kp = 0; kp < 192; kp++) {
                ull vI = wI[kp*16], vF = wF[kp*16], vG = wG[kp*16], vO = wO[kp*16];
                ull xv0 = x0[kp], xv1 = x1[kp], xv2 = x2[kp], xv3 = x3[kp];
                FFMA2(aI[0], vI, xv0); FFMA2(aI[1], vI, xv1); FFMA2(aI[2], vI, xv2); FFMA2(aI[3], vI, xv3);
                FFMA2(aF[0], vF, xv0); FFMA2(aF[1], vF, xv1); FFMA2(aF[2], vF, xv2); FFMA2(aF[3], vF, xv3);
                FFMA2(aG[0], vG, xv0); FFMA2(aG[1], vG, xv1); FFMA2(aG[2], vG, xv2); FFMA2(aG[3], vG, xv3);
                FFMA2(aO[0], vO, xv0); FFMA2(aO[1], vO, xv1); FFMA2(aO[2], vO, xv2); FFMA2(aO[3], vO, xv3);
            }

            float* cdst = g_c[(t + 1) & 1];
            float* hdst = g_h[(t + 1) & 1];
            #pragma unroll
            for (int m = 0; m < 4; m++) {
                float2 pI = unpack2(aI[m]); float gi = pI.x + pI.y + bI;
                float2 pF = unpack2(aF[m]); float gf = pF.x + pF.y + bF;
                float2 pG = unpack2(aG[m]); float gg = pG.x + pG.y + bG;
                float2 pO = unpack2(aO[m]); float go = pO.x + pO.y + bO;
                float iv = sigm_f(gi);
                float fv = sigm_f(gf);
                float gv = tanh_f(gg);
                float ov = sigm_f(go);
                float cn = fmaf(fv, creg[m], iv * gv);
                creg[m] = cn;
                float hn = ov * tanh_f(cn);
                int b = bt*64 + bg*4 + m;
                cdst[b*HH + jj] = cn;
                hdst[b*HH + jj] = hn;
                out[WOFF + (size_t)b*TM1*HH + t*HH + jj] = hn;
            }
        }
        gbar(bid, ++bar);   // h/c(t+1) visible for next attention
    }
}

// ---------------- launch ----------------
extern "C" void kernel_launch(void* const* d_in, const int* in_sizes, int n_in,
                              void* d_out, int out_size)
{
    const float* in   = (const float*)d_in[0];
    const float* W1   = (const float*)d_in[1];
    const float* b1   = (const float*)d_in[2];
    const float* W2   = (const float*)d_in[3];
    const float* b2   = (const float*)d_in[4];
    const float* W3   = (const float*)d_in[5];
    const float* b3   = (const float*)d_in[6];
    const float* W_ih = (const float*)d_in[7];
    const float* W_hh = (const float*)d_in[8];
    const float* b_ih = (const float*)d_in[9];
    const float* b_hh = (const float*)d_in[10];
    float* out = (float*)d_out;

    cudaFuncSetAttribute(persist_kernel, cudaFuncAttributeMaxDynamicSharedMemorySize, SMEM_PERSIST);

    prep_kernel<<<148, 256>>>(W_ih, W_hh, b_ih, b_hh, W2);
    z2_kernel<<<1024, 256>>>(in, b2);
    persist_kernel<<<NBLK, 256, SMEM_PERSIST>>>(in, W1, b1, W3, b3, out);
}

// round 8
// speedup vs baseline: 1.9373x; 1.2739x over previous
#include <cuda_runtime.h>

#define BB   512
#define TM1  99
#define NF   128
#define HH   256
#define Z2W  100
#define WOFF (BB*TM1*NF)
#define NBLK 128
#define NTHR 512

typedef unsigned long long ull;

// ---------------- device scratch ----------------
__device__ float  g_z2[BB*NF*Z2W];        // [b][n][s(pad 100)]
__device__ float  g_h[2][BB*HH];
__device__ float  g_c[2][BB*HH];
__device__ float4 g_Wt4[384*256];         // [k][j] -> (Wi,Wf,Wg,Wo)
__device__ float  g_W2t[TM1*Z2W];
__device__ float  g_bias[1024];
__device__ volatile unsigned g_arrive[NBLK];
__device__ volatile unsigned g_release;

// ---------------- math helpers ----------------
__device__ __forceinline__ float ex2f(float x){ float y; asm("ex2.approx.f32 %0, %1;" : "=f"(y) : "f"(x)); return y; }
__device__ __forceinline__ float rcpf(float x){ float y; asm("rcp.approx.f32 %0, %1;" : "=f"(y) : "f"(x)); return y; }
__device__ __forceinline__ float tanha(float x){ float y; asm("tanh.approx.f32 %0, %1;" : "=f"(y) : "f"(x)); return y; }
__device__ __forceinline__ float tanh_f(float x){
    float a  = fabsf(x);
    float em = ex2f(a * -2.8853900817779268f);
    float r  = (1.0f - em) * rcpf(1.0f + em);
    return copysignf(r, x);
}
__device__ __forceinline__ float sigm_f(float x){
    float e = ex2f(x * -1.4426950408889634f);
    return rcpf(1.0f + e);
}
__device__ __forceinline__ float wsum(float v){
    #pragma unroll
    for (int o = 16; o; o >>= 1) v += __shfl_xor_sync(0xffffffffu, v, o);
    return v;
}
__device__ __forceinline__ float wmax(float v){
    #pragma unroll
    for (int o = 16; o; o >>= 1) v = fmaxf(v, __shfl_xor_sync(0xffffffffu, v, o));
    return v;
}
__device__ __forceinline__ ull pack2(float a, float b){ ull r; asm("mov.b64 %0, {%1,%2};" : "=l"(r) : "f"(a), "f"(b)); return r; }
__device__ __forceinline__ float2 unpack2(ull v){ float2 r; asm("mov.b64 {%0,%1}, %2;" : "=f"(r.x), "=f"(r.y) : "l"(v)); return r; }
#define FFMA2(d,a,b) asm("fma.rn.f32x2 %0, %1, %2, %0;" : "+l"(d) : "l"(a), "l"(b))

// ---------------- grid barrier (all NBLK CTAs co-resident) ----------------
__device__ __forceinline__ void gbar(int bid, unsigned k){
    __threadfence();
    __syncthreads();
    if (threadIdx.x == 0) g_arrive[bid] = k;
    if (bid == 0 && threadIdx.x < 32) {
        for (int i = threadIdx.x; i < NBLK; i += 32)
            while (g_arrive[i] < k) __nanosleep(20);
        __syncwarp();
        if (threadIdx.x == 0) g_release = k;
    }
    if (threadIdx.x == 0) {
        while (g_release < k) __nanosleep(20);
        __threadfence();                     // drop stale L1 lines
    }
    __syncthreads();
}

// ---------------- prep ----------------
__global__ void prep_kernel(const float* __restrict__ W_ih, const float* __restrict__ W_hh,
                            const float* __restrict__ b_ih, const float* __restrict__ b_hh,
                            const float* __restrict__ W2)
{
    int stride = gridDim.x * blockDim.x;
    int tid0   = blockIdx.x * blockDim.x + threadIdx.x;

    for (int idx = tid0; idx < 384*256; idx += stride) {
        int k = idx >> 8, j = idx & 255;
        float4 v;
        if (k < 128) {
            v.x = W_ih[(j      )*128 + k];
            v.y = W_ih[(j + 256)*128 + k];
            v.z = W_ih[(j + 512)*128 + k];
            v.w = W_ih[(j + 768)*128 + k];
        } else {
            int kk = k - 128;
            v.x = W_hh[(j      )*256 + kk];
            v.y = W_hh[(j + 256)*256 + kk];
            v.z = W_hh[(j + 512)*256 + kk];
            v.w = W_hh[(j + 768)*256 + kk];
        }
        g_Wt4[idx] = v;
    }
    for (int idx = tid0; idx < TM1*Z2W; idx += stride) {
        int t = idx / Z2W, s = idx - t*Z2W;
        g_W2t[idx] = (s < TM1) ? W2[s*TM1 + t] : 0.0f;
    }
    for (int idx = tid0; idx < 1024; idx += stride)
        g_bias[idx] = b_ih[idx] + b_hh[idx];
    for (int idx = tid0; idx < BB*HH; idx += stride) {
        g_h[0][idx] = 0.0f;
        g_c[0][idx] = 0.0f;
    }
    if (blockIdx.x == 0) {
        if (threadIdx.x < NBLK) g_arrive[threadIdx.x] = 0;
        if (threadIdx.x == 0)   g_release = 0;
    }
}

// ---------------- z2 precompute ----------------
__global__ void z2_kernel(const float* __restrict__ in, const float* __restrict__ b2)
{
    __shared__ float inT[64*TM1];
    int b  = blockIdx.x >> 1;
    int nh = blockIdx.x & 1;
    int tid = threadIdx.x;

    for (int i = tid; i < 64*TM1; i += 256) {
        int t = i >> 6, nn = i & 63;
        inT[nn*TM1 + t] = in[b*TM1*NF + t*NF + nh*64 + nn];
    }
    __syncthreads();

    int w = tid >> 5, l = tid & 31;
    if (l < 25) {
        int s0 = 4*l;
        float4 bb;
        bb.x = (s0+0 < TM1) ? b2[s0+0] : 0.0f;
        bb.y = (s0+1 < TM1) ? b2[s0+1] : 0.0f;
        bb.z = (s0+2 < TM1) ? b2[s0+2] : 0.0f;
        bb.w = (s0+3 < TM1) ? b2[s0+3] : 0.0f;
        const float4* wrow = (const float4*)g_W2t;
        for (int nn = w*8; nn < w*8 + 8; nn++) {
            float4 acc = make_float4(0.f,0.f,0.f,0.f);
            #pragma unroll 3
            for (int t = 0; t < TM1; t++) {
                float  xv = inT[nn*TM1 + t];
                float4 wv = wrow[t*25 + l];
                acc.x = fmaf(xv, wv.x, acc.x);
                acc.y = fmaf(xv, wv.y, acc.y);
                acc.z = fmaf(xv, wv.z, acc.z);
                acc.w = fmaf(xv, wv.w, acc.w);
            }
            acc.x += bb.x; acc.y += bb.y; acc.z += bb.z; acc.w += bb.w;
            int n = nh*64 + nn;
            *(float4*)&g_z2[(b*NF + n)*Z2W + s0] = acc;
        }
    }
}

// ---------------- persistent fused kernel ----------------
// grid = 128 x 512. dyn smem: wsmu 98304B | xsf (64x386f) 98816B | attn 12288B
#define SMEM_PERSIST (52352*4)
__global__ __launch_bounds__(NTHR, 1) void persist_kernel(
    const float* __restrict__ in, const float* __restrict__ W1, const float* __restrict__ b1,
    const float* __restrict__ W3, const float* __restrict__ b3, float* __restrict__ out)
{
    extern __shared__ float sm[];
    ull*   wsmu = (ull*)sm;                  // [gate][kp][q] : (w[2kp],w[2kp+1])
    float* xsf  = sm + 24576;                // [bb][k], row stride 386
    float* hc   = sm + 49280;                // 4*512
    float* z1s  = sm + 51328;                // 4*128
    float* es   = sm + 51840;                // 4*128

    int bid = blockIdx.x, tid = threadIdx.x;
    int wrp = tid >> 5, l = tid & 31;
    int jt  = bid >> 3, bt = bid & 7;        // 16 j-tiles x 8 b-tiles

    // stage weight slice into smem once
    for (int idx = tid; idx < 192*16; idx += NTHR) {
        int kp = idx >> 4, q2 = idx & 15;
        int j  = jt*16 + q2;
        float4 w0 = g_Wt4[(2*kp  )*256 + j];
        float4 w1 = g_Wt4[(2*kp+1)*256 + j];
        wsmu[(0*192 + kp)*16 + q2] = pack2(w0.x, w1.x);
        wsmu[(1*192 + kp)*16 + q2] = pack2(w0.y, w1.y);
        wsmu[(2*192 + kp)*16 + q2] = pack2(w0.z, w1.z);
        wsmu[(3*192 + kp)*16 + q2] = pack2(w0.w, w1.w);
    }

    // GEMM mapping: q = hidden unit, bg = 4-batch group, kh = k-half
    int q  = tid & 15, bg = (tid >> 4) & 15, kh = tid >> 8;
    int jj = jt*16 + q;
    float bI = g_bias[jj], bF = g_bias[256+jj], bG = g_bias[512+jj], bO = g_bias[768+jj];
    float creg[4] = {0.f, 0.f, 0.f, 0.f};    // live in kh==0 threads
    __syncthreads();

    unsigned bar = 0;
    for (int t = 0; t < TM1; t++) {
        const float* hsrc = g_h[t & 1];
        const float* csrc = g_c[t & 1];

        // ============ ATTENTION (batches bid*4 .. +3) ============
        {
            int b0 = bid * 4;
            for (int i = tid; i < 4*512; i += NTHR) {
                int bi = i >> 9, j = i & 511;
                hc[i] = (j < 256) ? hsrc[(b0+bi)*HH + j] : csrc[(b0+bi)*HH + (j-256)];
            }
            __syncthreads();

            float4 hr[4][4];
            #pragma unroll
            for (int bi = 0; bi < 4; bi++) {
                const float4* h4 = (const float4*)(hc + bi*512);
                #pragma unroll
                for (int u = 0; u < 4; u++) hr[bi][u] = h4[l + 32*u];
            }

            for (int s = wrp; s < TM1; s += 16) {
                const float4* wr = (const float4*)(W1 + s*512);
                float4 w0 = wr[l], w1v = wr[l+32], w2v = wr[l+64], w3v = wr[l+96];
                float bv = b1[s];
                #pragma unroll
                for (int bi = 0; bi < 4; bi++) {
                    float a = 0.0f;
                    a = fmaf(w0.x, hr[bi][0].x, a);  a = fmaf(w0.y, hr[bi][0].y, a);
                    a = fmaf(w0.z, hr[bi][0].z, a);  a = fmaf(w0.w, hr[bi][0].w, a);
                    a = fmaf(w1v.x, hr[bi][1].x, a); a = fmaf(w1v.y, hr[bi][1].y, a);
                    a = fmaf(w1v.z, hr[bi][1].z, a); a = fmaf(w1v.w, hr[bi][1].w, a);
                    a = fmaf(w2v.x, hr[bi][2].x, a); a = fmaf(w2v.y, hr[bi][2].y, a);
                    a = fmaf(w2v.z, hr[bi][2].z, a); a = fmaf(w2v.w, hr[bi][2].w, a);
                    a = fmaf(w3v.x, hr[bi][3].x, a); a = fmaf(w3v.y, hr[bi][3].y, a);
                    a = fmaf(w3v.z, hr[bi][3].z, a); a = fmaf(w3v.w, hr[bi][3].w, a);
                    a = wsum(a);
                    if (l == 0) z1s[bi*128 + s] = a + bv;
                }
            }
            __syncthreads();

            for (int idx = wrp; idx < 512; idx += 16) {
                int bi = idx >> 7, n = idx & 127;
                const float* zrow = g_z2 + ((size_t)(b0+bi)*NF + n)*Z2W;
                const float* z1r  = z1s + bi*128;
                float acc = 0.0f;
                int s;
                s = l;      acc = fmaf(W3[s], tanha(z1r[s] + zrow[s]), acc);
                s = l + 32; acc = fmaf(W3[s], tanha(z1r[s] + zrow[s]), acc);
                s = l + 64; acc = fmaf(W3[s], tanha(z1r[s] + zrow[s]), acc);
                if (l < 3) { s = l + 96; acc = fmaf(W3[s], tanha(z1r[s] + zrow[s]), acc); }
                acc = wsum(acc);
                if (l == 0) es[bi*128 + n] = acc + b3[0];
            }
            __syncthreads();

            if (wrp < 4) {
                int bi = wrp, b = b0 + bi;
                float v0 = es[bi*128 + l],      v1 = es[bi*128 + 32 + l];
                float v2 = es[bi*128 + 64 + l], v3 = es[bi*128 + 96 + l];
                float m = wmax(fmaxf(fmaxf(v0, v1), fmaxf(v2, v3)));
                float e0 = ex2f((v0 - m) * 1.4426950408889634f);
                float e1 = ex2f((v1 - m) * 1.4426950408889634f);
                float e2 = ex2f((v2 - m) * 1.4426950408889634f);
                float e3 = ex2f((v3 - m) * 1.4426950408889634f);
                float r = rcpf(wsum(e0 + e1 + e2 + e3));
                const float* xrow = in  + (size_t)b*TM1*NF + t*NF;
                float*       orow = out + (size_t)b*TM1*NF + t*NF;
                orow[l     ] = e0 * r * xrow[l     ];
                orow[l + 32] = e1 * r * xrow[l + 32];
                orow[l + 64] = e2 * r * xrow[l + 64];
                orow[l + 96] = e3 * r * xrow[l + 96];
            }
        }
        gbar(bid, ++bar);   // w(t) visible everywhere; h/c reads done

        // ============ LSTM GEMM + cell (64 batches x 16 j, k split in 2) ====
        {
            for (int i = tid; i < 64*384; i += NTHR) {
                int bb = i / 384, k = i - bb*384;
                int b  = bt*64 + bb;
                float v = (k < NF) ? out[(size_t)b*TM1*NF + t*NF + k]
                                   : hsrc[b*HH + (k - NF)];
                xsf[bb*386 + k] = v;
            }
            __syncthreads();

            const ull* xu = (const ull*)xsf;
            const ull* x0 = xu + (bg*4 + 0)*193 + kh*96;
            const ull* x1 = xu + (bg*4 + 1)*193 + kh*96;
            const ull* x2 = xu + (bg*4 + 2)*193 + kh*96;
            const ull* x3 = xu + (bg*4 + 3)*193 + kh*96;
            const ull* wI = wsmu + (0*192 + kh*96)*16 + q;
            const ull* wF = wsmu + (1*192 + kh*96)*16 + q;
            const ull* wG = wsmu + (2*192 + kh*96)*16 + q;
            const ull* wO = wsmu + (3*192 + kh*96)*16 + q;

            ull aI[4] = {0,0,0,0}, aF[4] = {0,0,0,0}, aG[4] = {0,0,0,0}, aO[4] = {0,0,0,0};

            #pragma unroll 2
            for (int kp = 0; kp < 96; kp++) {
                ull vI = wI[kp*16], vF = wF[kp*16], vG = wG[kp*16], vO = wO[kp*16];
                ull xv0 = x0[kp], xv1 = x1[kp], xv2 = x2[kp], xv3 = x3[kp];
                FFMA2(aI[0], vI, xv0); FFMA2(aI[1], vI, xv1); FFMA2(aI[2], vI, xv2); FFMA2(aI[3], vI, xv3);
                FFMA2(aF[0], vF, xv0); FFMA2(aF[1], vF, xv1); FFMA2(aF[2], vF, xv2); FFMA2(aF[3], vF, xv3);
                FFMA2(aG[0], vG, xv0); FFMA2(aG[1], vG, xv1); FFMA2(aG[2], vG, xv2); FFMA2(aG[3], vG, xv3);
                FFMA2(aO[0], vO, xv0); FFMA2(aO[1], vO, xv1); FFMA2(aO[2], vO, xv2); FFMA2(aO[3], vO, xv3);
            }

            // combine k-halves through smem scratch (reuse xsf area)
            __syncthreads();
            ull* scratch = (ull*)xsf;
            if (kh == 1) {
                ull* d = scratch + (size_t)(bg*16 + q)*16;
                d[0]  = aI[0]; d[1]  = aI[1]; d[2]  = aI[2]; d[3]  = aI[3];
                d[4]  = aF[0]; d[5]  = aF[1]; d[6]  = aF[2]; d[7]  = aF[3];
                d[8]  = aG[0]; d[9]  = aG[1]; d[10] = aG[2]; d[11] = aG[3];
                d[12] = aO[0]; d[13] = aO[1]; d[14] = aO[2]; d[15] = aO[3];
            }
            __syncthreads();

            if (kh == 0) {
                const ull* d = scratch + (size_t)(bg*16 + q)*16;
                float* cdst = g_c[(t + 1) & 1];
                float* hdst = g_h[(t + 1) & 1];
                #pragma unroll
                for (int m = 0; m < 4; m++) {
                    float2 pI = unpack2(aI[m]), rI = unpack2(d[m]);
                    float2 pF = unpack2(aF[m]), rF = unpack2(d[4+m]);
                    float2 pG = unpack2(aG[m]), rG = unpack2(d[8+m]);
                    float2 pO = unpack2(aO[m]), rO = unpack2(d[12+m]);
                    float gi = (pI.x + pI.y) + (rI.x + rI.y) + bI;
                    float gf = (pF.x + pF.y) + (rF.x + rF.y) + bF;
                    float gg = (pG.x + pG.y) + (rG.x + rG.y) + bG;
                    float go = (pO.x + pO.y) + (rO.x + rO.y) + bO;
                    float iv = sigm_f(gi);
                    float fv = sigm_f(gf);
                    float gv = tanh_f(gg);
                    float ov = sigm_f(go);
                    float cn = fmaf(fv, creg[m], iv * gv);
                    creg[m] = cn;
                    float hn = ov * tanh_f(cn);
                    int b = bt*64 + bg*4 + m;
                    cdst[b*HH + jj] = cn;
                    hdst[b*HH + jj] = hn;
                    out[WOFF + (size_t)b*TM1*HH + t*HH + jj] = hn;
                }
            }
        }
        gbar(bid, ++bar);   // h/c(t+1) visible for next attention
    }
}

// ---------------- launch ----------------
extern "C" void kernel_launch(void* const* d_in, const int* in_sizes, int n_in,
                              void* d_out, int out_size)
{
    const float* in   = (const float*)d_in[0];
    const float* W1   = (const float*)d_in[1];
    const float* b1   = (const float*)d_in[2];
    const float* W2   = (const float*)d_in[3];
    const float* b2   = (const float*)d_in[4];
    const float* W3   = (const float*)d_in[5];
    const float* b3   = (const float*)d_in[6];
    const float* W_ih = (const float*)d_in[7];
    const float* W_hh = (const float*)d_in[8];
    const float* b_ih = (const float*)d_in[9];
    const float* b_hh = (const float*)d_in[10];
    float* out = (float*)d_out;

    cudaFuncSetAttribute(persist_kernel, cudaFuncAttributeMaxDynamicSharedMemorySize, SMEM_PERSIST);

    prep_kernel<<<148, 256>>>(W_ih, W_hh, b_ih, b_hh, W2);
    z2_kernel<<<1024, 256>>>(in, b2);
    persist_kernel<<<NBLK, NTHR, SMEM_PERSIST>>>(in, W1, b1, W3, b3, out);
}

// round 9
// speedup vs baseline: 2.2210x; 1.1464x over previous
#include <cuda_runtime.h>

#define BB   512
#define TM1  99
#define NF   128
#define HH   256
#define Z2W  100
#define WOFF (BB*TM1*NF)
#define NBLK 128
#define NTHR 512
#define NGRP 8                 // 8 independent groups of 16 CTAs

typedef unsigned long long ull;

// ---------------- device scratch ----------------
__device__ float  g_z2[BB*NF*Z2W];        // [b][n][s(pad 100)]
__device__ float  g_h[2][BB*HH];
__device__ float  g_c[2][BB*HH];
__device__ float4 g_Wt4[384*256];         // [k][j] -> (Wi,Wf,Wg,Wo)
__device__ float  g_W2t[TM1*Z2W];
__device__ float  g_bias[1024];

// group barrier state: each counter/release on its own 128B line
struct __align__(128) PadU { unsigned v; unsigned pad[31]; };
__device__ PadU g_cnt[NGRP];
__device__ PadU g_rel[NGRP];

// ---------------- math helpers ----------------
__device__ __forceinline__ float ex2f(float x){ float y; asm("ex2.approx.f32 %0, %1;" : "=f"(y) : "f"(x)); return y; }
__device__ __forceinline__ float rcpf(float x){ float y; asm("rcp.approx.f32 %0, %1;" : "=f"(y) : "f"(x)); return y; }
__device__ __forceinline__ float tanha(float x){ float y; asm("tanh.approx.f32 %0, %1;" : "=f"(y) : "f"(x)); return y; }
__device__ __forceinline__ float tanh_f(float x){
    float a  = fabsf(x);
    float em = ex2f(a * -2.8853900817779268f);
    float r  = (1.0f - em) * rcpf(1.0f + em);
    return copysignf(r, x);
}
__device__ __forceinline__ float sigm_f(float x){
    float e = ex2f(x * -1.4426950408889634f);
    return rcpf(1.0f + e);
}
__device__ __forceinline__ float wsum(float v){
    #pragma unroll
    for (int o = 16; o; o >>= 1) v += __shfl_xor_sync(0xffffffffu, v, o);
    return v;
}
__device__ __forceinline__ float wmax(float v){
    #pragma unroll
    for (int o = 16; o; o >>= 1) v = fmaxf(v, __shfl_xor_sync(0xffffffffu, v, o));
    return v;
}
__device__ __forceinline__ ull pack2(float a, float b){ ull r; asm("mov.b64 %0, {%1,%2};" : "=l"(r) : "f"(a), "f"(b)); return r; }
__device__ __forceinline__ float2 unpack2(ull v){ float2 r; asm("mov.b64 {%0,%1}, %2;" : "=f"(r.x), "=f"(r.y) : "l"(v)); return r; }
#define FFMA2(d,a,b) asm("fma.rn.f32x2 %0, %1, %2, %0;" : "+l"(d) : "l"(a), "l"(b))

// ---------------- group-local barrier (16 CTAs per group) ----------------
__device__ __forceinline__ void groupbar(int g, unsigned e){
    __threadfence();                         // release: my global writes visible
    __syncthreads();
    if (threadIdx.x == 0) {
        unsigned old = atomicAdd(&g_cnt[g].v, 1u);
        if ((old & 15u) == 15u) {
            *((volatile unsigned*)&g_rel[g].v) = e;     // last arriver releases
        } else {
            while (*((volatile unsigned*)&g_rel[g].v) < e) { }
        }
        __threadfence();                     // acquire + drop stale L1 lines
    }
    __syncthreads();
}

// ---------------- prep ----------------
__global__ void prep_kernel(const float* __restrict__ W_ih, const float* __restrict__ W_hh,
                            const float* __restrict__ b_ih, const float* __restrict__ b_hh,
                            const float* __restrict__ W2)
{
    int stride = gridDim.x * blockDim.x;
    int tid0   = blockIdx.x * blockDim.x + threadIdx.x;

    for (int idx = tid0; idx < 384*256; idx += stride) {
        int k = idx >> 8, j = idx & 255;
        float4 v;
        if (k < 128) {
            v.x = W_ih[(j      )*128 + k];
            v.y = W_ih[(j + 256)*128 + k];
            v.z = W_ih[(j + 512)*128 + k];
            v.w = W_ih[(j + 768)*128 + k];
        } else {
            int kk = k - 128;
            v.x = W_hh[(j      )*256 + kk];
            v.y = W_hh[(j + 256)*256 + kk];
            v.z = W_hh[(j + 512)*256 + kk];
            v.w = W_hh[(j + 768)*256 + kk];
        }
        g_Wt4[idx] = v;
    }
    for (int idx = tid0; idx < TM1*Z2W; idx += stride) {
        int t = idx / Z2W, s = idx - t*Z2W;
        g_W2t[idx] = (s < TM1) ? W2[s*TM1 + t] : 0.0f;
    }
    for (int idx = tid0; idx < 1024; idx += stride)
        g_bias[idx] = b_ih[idx] + b_hh[idx];
    for (int idx = tid0; idx < BB*HH; idx += stride) {
        g_h[0][idx] = 0.0f;
        g_c[0][idx] = 0.0f;
    }
    // reset barrier state every replay
    if (blockIdx.x == 0 && threadIdx.x < NGRP) {
        g_cnt[threadIdx.x].v = 0;
        g_rel[threadIdx.x].v = 0;
    }
}

// ---------------- z2 precompute ----------------
__global__ void z2_kernel(const float* __restrict__ in, const float* __restrict__ b2)
{
    __shared__ float inT[64*TM1];
    int b  = blockIdx.x >> 1;
    int nh = blockIdx.x & 1;
    int tid = threadIdx.x;

    for (int i = tid; i < 64*TM1; i += 256) {
        int t = i >> 6, nn = i & 63;
        inT[nn*TM1 + t] = in[b*TM1*NF + t*NF + nh*64 + nn];
    }
    __syncthreads();

    int w = tid >> 5, l = tid & 31;
    if (l < 25) {
        int s0 = 4*l;
        float4 bb;
        bb.x = (s0+0 < TM1) ? b2[s0+0] : 0.0f;
        bb.y = (s0+1 < TM1) ? b2[s0+1] : 0.0f;
        bb.z = (s0+2 < TM1) ? b2[s0+2] : 0.0f;
        bb.w = (s0+3 < TM1) ? b2[s0+3] : 0.0f;
        const float4* wrow = (const float4*)g_W2t;
        for (int nn = w*8; nn < w*8 + 8; nn++) {
            float4 acc = make_float4(0.f,0.f,0.f,0.f);
            #pragma unroll 3
            for (int t = 0; t < TM1; t++) {
                float  xv = inT[nn*TM1 + t];
                float4 wv = wrow[t*25 + l];
                acc.x = fmaf(xv, wv.x, acc.x);
                acc.y = fmaf(xv, wv.y, acc.y);
                acc.z = fmaf(xv, wv.z, acc.z);
                acc.w = fmaf(xv, wv.w, acc.w);
            }
            acc.x += bb.x; acc.y += bb.y; acc.z += bb.z; acc.w += bb.w;
            int n = nh*64 + nn;
            *(float4*)&g_z2[(b*NF + n)*Z2W + s0] = acc;
        }
    }
}

// ---------------- persistent fused kernel ----------------
// grid = 128 x 512. block = (g = bid>>4 batch-group, u = bid&15).
// attention: batches g*64+u*4 ..+4.  LSTM: j-tile u, batches g*64..+64.
// dyn smem: wsmu 98304B | xsf (64x386f) 98816B | attn 12288B
#define SMEM_PERSIST (52352*4)
__global__ __launch_bounds__(NTHR, 1) void persist_kernel(
    const float* __restrict__ in, const float* __restrict__ W1, const float* __restrict__ b1,
    const float* __restrict__ W3, const float* __restrict__ b3, float* __restrict__ out)
{
    extern __shared__ float sm[];
    ull*   wsmu = (ull*)sm;                  // [gate][kp][q] : (w[2kp],w[2kp+1])
    float* xsf  = sm + 24576;                // [bb][k], row stride 386
    float* hc   = sm + 49280;                // 4*512
    float* z1s  = sm + 51328;                // 4*128
    float* es   = sm + 51840;                // 4*128

    int bid = blockIdx.x, tid = threadIdx.x;
    int wrp = tid >> 5, l = tid & 31;
    int grp = bid >> 4, u = bid & 15;        // group, lane-in-group
    int jt  = u, bt = grp;                   // j-tile, batch-tile

    // stage weight slice into smem once
    for (int idx = tid; idx < 192*16; idx += NTHR) {
        int kp = idx >> 4, q2 = idx & 15;
        int j  = jt*16 + q2;
        float4 w0 = g_Wt4[(2*kp  )*256 + j];
        float4 w1 = g_Wt4[(2*kp+1)*256 + j];
        wsmu[(0*192 + kp)*16 + q2] = pack2(w0.x, w1.x);
        wsmu[(1*192 + kp)*16 + q2] = pack2(w0.y, w1.y);
        wsmu[(2*192 + kp)*16 + q2] = pack2(w0.z, w1.z);
        wsmu[(3*192 + kp)*16 + q2] = pack2(w0.w, w1.w);
    }

    // GEMM mapping: q = hidden unit, bg = 4-batch group, kh = k-half
    int q  = tid & 15, bg = (tid >> 4) & 15, kh = tid >> 8;
    int jj = jt*16 + q;
    float bI = g_bias[jj], bF = g_bias[256+jj], bG = g_bias[512+jj], bO = g_bias[768+jj];
    float creg[4] = {0.f, 0.f, 0.f, 0.f};    // live in kh==0 threads
    __syncthreads();

    unsigned bar = 0;
    for (int t = 0; t < TM1; t++) {
        const float* hsrc = g_h[t & 1];
        const float* csrc = g_c[t & 1];

        // ============ ATTENTION (batches grp*64 + u*4 .. +3) ============
        {
            int b0 = grp*64 + u*4;
            for (int i = tid; i < 4*512; i += NTHR) {
                int bi = i >> 9, j = i & 511;
                hc[i] = (j < 256) ? hsrc[(b0+bi)*HH + j] : csrc[(b0+bi)*HH + (j-256)];
            }
            __syncthreads();

            float4 hr[4][4];
            #pragma unroll
            for (int bi = 0; bi < 4; bi++) {
                const float4* h4 = (const float4*)(hc + bi*512);
                #pragma unroll
                for (int u4 = 0; u4 < 4; u4++) hr[bi][u4] = h4[l + 32*u4];
            }

            for (int s = wrp; s < TM1; s += 16) {
                const float4* wr = (const float4*)(W1 + s*512);
                float4 w0 = wr[l], w1v = wr[l+32], w2v = wr[l+64], w3v = wr[l+96];
                float bv = b1[s];
                #pragma unroll
                for (int bi = 0; bi < 4; bi++) {
                    float a = 0.0f;
                    a = fmaf(w0.x, hr[bi][0].x, a);  a = fmaf(w0.y, hr[bi][0].y, a);
                    a = fmaf(w0.z, hr[bi][0].z, a);  a = fmaf(w0.w, hr[bi][0].w, a);
                    a = fmaf(w1v.x, hr[bi][1].x, a); a = fmaf(w1v.y, hr[bi][1].y, a);
                    a = fmaf(w1v.z, hr[bi][1].z, a); a = fmaf(w1v.w, hr[bi][1].w, a);
                    a = fmaf(w2v.x, hr[bi][2].x, a); a = fmaf(w2v.y, hr[bi][2].y, a);
                    a = fmaf(w2v.z, hr[bi][2].z, a); a = fmaf(w2v.w, hr[bi][2].w, a);
                    a = fmaf(w3v.x, hr[bi][3].x, a); a = fmaf(w3v.y, hr[bi][3].y, a);
                    a = fmaf(w3v.z, hr[bi][3].z, a); a = fmaf(w3v.w, hr[bi][3].w, a);
                    a = wsum(a);
                    if (l == 0) z1s[bi*128 + s] = a + bv;
                }
            }
            __syncthreads();

            for (int idx = wrp; idx < 512; idx += 16) {
                int bi = idx >> 7, n = idx & 127;
                const float* zrow = g_z2 + ((size_t)(b0+bi)*NF + n)*Z2W;
                const float* z1r  = z1s + bi*128;
                float acc = 0.0f;
                int s;
                s = l;      acc = fmaf(W3[s], tanha(z1r[s] + zrow[s]), acc);
                s = l + 32; acc = fmaf(W3[s], tanha(z1r[s] + zrow[s]), acc);
                s = l + 64; acc = fmaf(W3[s], tanha(z1r[s] + zrow[s]), acc);
                if (l < 3) { s = l + 96; acc = fmaf(W3[s], tanha(z1r[s] + zrow[s]), acc); }
                acc = wsum(acc);
                if (l == 0) es[bi*128 + n] = acc + b3[0];
            }
            __syncthreads();

            if (wrp < 4) {
                int bi = wrp, b = b0 + bi;
                float v0 = es[bi*128 + l],      v1 = es[bi*128 + 32 + l];
                float v2 = es[bi*128 + 64 + l], v3 = es[bi*128 + 96 + l];
                float m = wmax(fmaxf(fmaxf(v0, v1), fmaxf(v2, v3)));
                float e0 = ex2f((v0 - m) * 1.4426950408889634f);
                float e1 = ex2f((v1 - m) * 1.4426950408889634f);
                float e2 = ex2f((v2 - m) * 1.4426950408889634f);
                float e3 = ex2f((v3 - m) * 1.4426950408889634f);
                float r = rcpf(wsum(e0 + e1 + e2 + e3));
                const float* xrow = in  + (size_t)b*TM1*NF + t*NF;
                float*       orow = out + (size_t)b*TM1*NF + t*NF;
                orow[l     ] = e0 * r * xrow[l     ];
                orow[l + 32] = e1 * r * xrow[l + 32];
                orow[l + 64] = e2 * r * xrow[l + 64];
                orow[l + 96] = e3 * r * xrow[l + 96];
            }
        }
        groupbar(grp, ++bar);   // w(t) visible within group; h/c reads done

        // ============ LSTM GEMM + cell (64 batches x 16 j, k split in 2) ====
        {
            for (int i = tid; i < 64*384; i += NTHR) {
                int bb = i / 384, k = i - bb*384;
                int b  = bt*64 + bb;
                float v = (k < NF) ? out[(size_t)b*TM1*NF + t*NF + k]
                                   : hsrc[b*HH + (k - NF)];
                xsf[bb*386 + k] = v;
            }
            __syncthreads();

            const ull* xu = (const ull*)xsf;
            const ull* x0 = xu + (bg*4 + 0)*193 + kh*96;
            const ull* x1 = xu + (bg*4 + 1)*193 + kh*96;
            const ull* x2 = xu + (bg*4 + 2)*193 + kh*96;
            const ull* x3 = xu + (bg*4 + 3)*193 + kh*96;
            const ull* wI = wsmu + (0*192 + kh*96)*16 + q;
            const ull* wF = wsmu + (1*192 + kh*96)*16 + q;
            const ull* wG = wsmu + (2*192 + kh*96)*16 + q;
            const ull* wO = wsmu + (3*192 + kh*96)*16 + q;

            ull aI[4] = {0,0,0,0}, aF[4] = {0,0,0,0}, aG[4] = {0,0,0,0}, aO[4] = {0,0,0,0};

            #pragma unroll 2
            for (int kp = 0; kp < 96; kp++) {
                ull vI = wI[kp*16], vF = wF[kp*16], vG = wG[kp*16], vO = wO[kp*16];
                ull xv0 = x0[kp], xv1 = x1[kp], xv2 = x2[kp], xv3 = x3[kp];
                FFMA2(aI[0], vI, xv0); FFMA2(aI[1], vI, xv1); FFMA2(aI[2], vI, xv2); FFMA2(aI[3], vI, xv3);
                FFMA2(aF[0], vF, xv0); FFMA2(aF[1], vF, xv1); FFMA2(aF[2], vF, xv2); FFMA2(aF[3], vF, xv3);
                FFMA2(aG[0], vG, xv0); FFMA2(aG[1], vG, xv1); FFMA2(aG[2], vG, xv2); FFMA2(aG[3], vG, xv3);
                FFMA2(aO[0], vO, xv0); FFMA2(aO[1], vO, xv1); FFMA2(aO[2], vO, xv2); FFMA2(aO[3], vO, xv3);
            }

            // combine k-halves through smem scratch (reuse xsf area)
            __syncthreads();
            ull* scratch = (ull*)xsf;
            if (kh == 1) {
                ull* d = scratch + (size_t)(bg*16 + q)*16;
                d[0]  = aI[0]; d[1]  = aI[1]; d[2]  = aI[2]; d[3]  = aI[3];
                d[4]  = aF[0]; d[5]  = aF[1]; d[6]  = aF[2]; d[7]  = aF[3];
                d[8]  = aG[0]; d[9]  = aG[1]; d[10] = aG[2]; d[11] = aG[3];
                d[12] = aO[0]; d[13] = aO[1]; d[14] = aO[2]; d[15] = aO[3];
            }
            __syncthreads();

            if (kh == 0) {
                const ull* d = scratch + (size_t)(bg*16 + q)*16;
                float* cdst = g_c[(t + 1) & 1];
                float* hdst = g_h[(t + 1) & 1];
                #pragma unroll
                for (int m = 0; m < 4; m++) {
                    float2 pI = unpack2(aI[m]), rI = unpack2(d[m]);
                    float2 pF = unpack2(aF[m]), rF = unpack2(d[4+m]);
                    float2 pG = unpack2(aG[m]), rG = unpack2(d[8+m]);
                    float2 pO = unpack2(aO[m]), rO = unpack2(d[12+m]);
                    float gi = (pI.x + pI.y) + (rI.x + rI.y) + bI;
                    float gf = (pF.x + pF.y) + (rF.x + rF.y) + bF;
                    float gg = (pG.x + pG.y) + (rG.x + rG.y) + bG;
                    float go = (pO.x + pO.y) + (rO.x + rO.y) + bO;
                    float iv = sigm_f(gi);
                    float fv = sigm_f(gf);
                    float gv = tanh_f(gg);
                    float ov = sigm_f(go);
                    float cn = fmaf(fv, creg[m], iv * gv);
                    creg[m] = cn;
                    float hn = ov * tanh_f(cn);
                    int b = bt*64 + bg*4 + m;
                    cdst[b*HH + jj] = cn;
                    hdst[b*HH + jj] = hn;
                    out[WOFF + (size_t)b*TM1*HH + t*HH + jj] = hn;
                }
            }
        }
        groupbar(grp, ++bar);   // h/c(t+1) visible within group
    }
}

// ---------------- launch ----------------
extern "C" void kernel_launch(void* const* d_in, const int* in_sizes, int n_in,
                              void* d_out, int out_size)
{
    const float* in   = (const float*)d_in[0];
    const float* W1   = (const float*)d_in[1];
    const float* b1   = (const float*)d_in[2];
    const float* W2   = (const float*)d_in[3];
    const float* b2   = (const float*)d_in[4];
    const float* W3   = (const float*)d_in[5];
    const float* b3   = (const float*)d_in[6];
    const float* W_ih = (const float*)d_in[7];
    const float* W_hh = (const float*)d_in[8];
    const float* b_ih = (const float*)d_in[9];
    const float* b_hh = (const float*)d_in[10];
    float* out = (float*)d_out;

    cudaFuncSetAttribute(persist_kernel, cudaFuncAttributeMaxDynamicSharedMemorySize, SMEM_PERSIST);

    prep_kernel<<<148, 256>>>(W_ih, W_hh, b_ih, b_hh, W2);
    z2_kernel<<<1024, 256>>>(in, b2);
    persist_kernel<<<NBLK, NTHR, SMEM_PERSIST>>>(in, W1, b1, W3, b3, out);
}

// round 12
// speedup vs baseline: 2.5681x; 1.1563x over previous
#include <cuda_runtime.h>

#define BB   512
#define TM1  99
#define NF   128
#define HH   256
#define WOFF (BB*TM1*NF)
#define NBLK 128
#define NTHR 512
#define NGRP 8                 // 8 independent groups of 16 CTAs

typedef unsigned long long ull;

// ---------------- device scratch ----------------
__device__ float  g_z2T[(size_t)BB*TM1*NF]; // transposed: [b][s][n]
__device__ float  g_h[2][BB*HH];
__device__ float  g_c[2][BB*HH];
__device__ float4 g_Wt4[384*256];         // [k][j] -> (Wi,Wf,Wg,Wo)
__device__ ull    g_W1T2[256*128];        // [kp][s] -> (W1[s][2kp], W1[s][2kp+1]), s pad 128
__device__ float  g_W2t[TM1*100];         // W2 transposed [t][s], s pad 100
__device__ float  g_bias[1024];

// group barrier state: each counter/release on its own 128B line
struct __align__(128) PadU { unsigned v; unsigned pad[31]; };
__device__ PadU g_cnt[NGRP];
__device__ PadU g_rel[NGRP];

// ---------------- math helpers ----------------
__device__ __forceinline__ float ex2f(float x){ float y; asm("ex2.approx.f32 %0, %1;" : "=f"(y) : "f"(x)); return y; }
__device__ __forceinline__ float rcpf(float x){ float y; asm("rcp.approx.f32 %0, %1;" : "=f"(y) : "f"(x)); return y; }
__device__ __forceinline__ float tanha(float x){ float y; asm("tanh.approx.f32 %0, %1;" : "=f"(y) : "f"(x)); return y; }
__device__ __forceinline__ float tanh_f(float x){
    float a  = fabsf(x);
    float em = ex2f(a * -2.8853900817779268f);
    float r  = (1.0f - em) * rcpf(1.0f + em);
    return copysignf(r, x);
}
__device__ __forceinline__ float sigm_f(float x){
    float e = ex2f(x * -1.4426950408889634f);
    return rcpf(1.0f + e);
}
__device__ __forceinline__ float wsum(float v){
    #pragma unroll
    for (int o = 16; o; o >>= 1) v += __shfl_xor_sync(0xffffffffu, v, o);
    return v;
}
__device__ __forceinline__ float wmax(float v){
    #pragma unroll
    for (int o = 16; o; o >>= 1) v = fmaxf(v, __shfl_xor_sync(0xffffffffu, v, o));
    return v;
}
__device__ __forceinline__ ull pack2(float a, float b){ ull r; asm("mov.b64 %0, {%1,%2};" : "=l"(r) : "f"(a), "f"(b)); return r; }
__device__ __forceinline__ float2 unpack2(ull v){ float2 r; asm("mov.b64 {%0,%1}, %2;" : "=f"(r.x), "=f"(r.y) : "l"(v)); return r; }
#define FFMA2(d,a,b) asm("fma.rn.f32x2 %0, %1, %2, %0;" : "+l"(d) : "l"(a), "l"(b))

// ---------------- group-local barrier (16 CTAs per group) ----------------
__device__ __forceinline__ void groupbar(int g, unsigned e){
    __threadfence();                         // release
    __syncthreads();
    if (threadIdx.x == 0) {
        unsigned old = atomicAdd(&g_cnt[g].v, 1u);
        if ((old & 15u) == 15u) {
            *((volatile unsigned*)&g_rel[g].v) = e;
        } else {
            while (*((volatile unsigned*)&g_rel[g].v) < e) { }
        }
        __threadfence();                     // acquire + drop stale L1 lines
    }
    __syncthreads();
}

// ---------------- prep ----------------
__global__ void prep_kernel(const float* __restrict__ W_ih, const float* __restrict__ W_hh,
                            const float* __restrict__ b_ih, const float* __restrict__ b_hh,
                            const float* __restrict__ W2,   const float* __restrict__ W1)
{
    int stride = gridDim.x * blockDim.x;
    int tid0   = blockIdx.x * blockDim.x + threadIdx.x;

    for (int idx = tid0; idx < 384*256; idx += stride) {
        int k = idx >> 8, j = idx & 255;
        float4 v;
        if (k < 128) {
            v.x = W_ih[(j      )*128 + k];
            v.y = W_ih[(j + 256)*128 + k];
            v.z = W_ih[(j + 512)*128 + k];
            v.w = W_ih[(j + 768)*128 + k];
        } else {
            int kk = k - 128;
            v.x = W_hh[(j      )*256 + kk];
            v.y = W_hh[(j + 256)*256 + kk];
            v.z = W_hh[(j + 512)*256 + kk];
            v.w = W_hh[(j + 768)*256 + kk];
        }
        g_Wt4[idx] = v;
    }
    // W1 transposed + k-paired: [kp][s]
    for (int idx = tid0; idx < 256*128; idx += stride) {
        int kp = idx >> 7, s = idx & 127;
        ull v = 0;
        if (s < TM1) v = pack2(W1[s*512 + 2*kp], W1[s*512 + 2*kp + 1]);
        g_W1T2[idx] = v;
    }
    for (int idx = tid0; idx < TM1*100; idx += stride) {
        int t = idx / 100, s = idx - t*100;
        g_W2t[idx] = (s < TM1) ? W2[s*TM1 + t] : 0.0f;
    }
    for (int idx = tid0; idx < 1024; idx += stride)
        g_bias[idx] = b_ih[idx] + b_hh[idx];
    for (int idx = tid0; idx < BB*HH; idx += stride) {
        g_h[0][idx] = 0.0f;
        g_c[0][idx] = 0.0f;
    }
    if (blockIdx.x == 0 && threadIdx.x < NGRP) {
        g_cnt[threadIdx.x].v = 0;
        g_rel[threadIdx.x].v = 0;
    }
}

// ---------------- z2 precompute (store transposed [b][s][n]) ----------------
__global__ void z2_kernel(const float* __restrict__ in, const float* __restrict__ b2)
{
    __shared__ float inT[64*TM1];
    int b  = blockIdx.x >> 1;
    int nh = blockIdx.x & 1;
    int tid = threadIdx.x;

    for (int i = tid; i < 64*TM1; i += 256) {
        int t = i >> 6, nn = i & 63;
        inT[nn*TM1 + t] = in[b*TM1*NF + t*NF + nh*64 + nn];
    }
    __syncthreads();

    int w = tid >> 5, l = tid & 31;
    if (l < 25) {
        int s0 = 4*l;
        float4 bb;
        bb.x = (s0+0 < TM1) ? b2[s0+0] : 0.0f;
        bb.y = (s0+1 < TM1) ? b2[s0+1] : 0.0f;
        bb.z = (s0+2 < TM1) ? b2[s0+2] : 0.0f;
        bb.w = (s0+3 < TM1) ? b2[s0+3] : 0.0f;
        const float4* wrow = (const float4*)g_W2t;   // [t][25 float4]
        for (int nn = w*8; nn < w*8 + 8; nn++) {
            float4 acc = make_float4(0.f,0.f,0.f,0.f);
            #pragma unroll 3
            for (int t = 0; t < TM1; t++) {
                float  xv = inT[nn*TM1 + t];
                float4 wv = wrow[t*25 + l];
                acc.x = fmaf(xv, wv.x, acc.x);
                acc.y = fmaf(xv, wv.y, acc.y);
                acc.z = fmaf(xv, wv.z, acc.z);
                acc.w = fmaf(xv, wv.w, acc.w);
            }
            acc.x += bb.x; acc.y += bb.y; acc.z += bb.z; acc.w += bb.w;
            int n = nh*64 + nn;
            size_t base = ((size_t)b*TM1 + s0)*NF + n;
            g_z2T[base] = acc.x;
            if (s0+1 < TM1) g_z2T[base +   NF] = acc.y;
            if (s0+2 < TM1) g_z2T[base + 2*NF] = acc.z;
            // s0+3 == 99 is always out of range when s0 == 96
            if (s0+3 < TM1) g_z2T[base + 3*NF] = acc.w;
        }
    }
}

// ---------------- persistent fused kernel ----------------
// grid = 128 x 512. block = (grp = bid>>4, u = bid&15).
// attention: batches grp*64+u*4..+4.  LSTM: j-tile u, batches grp*64..+64.
// dyn smem (floats): wsmu 24576 | xsf 24832 (also z1p + GEMM scratch) |
//                    hc 2048 | z1s 512 | es 512 | w3s 128 | b1s 128
#define SMEM_PERSIST (52736*4)
__global__ __launch_bounds__(NTHR, 1) void persist_kernel(
    const float* __restrict__ in, const float* __restrict__ b1,
    const float* __restrict__ W3, const float* __restrict__ b3, float* __restrict__ out)
{
    extern __shared__ float sm[];
    ull*   wsmu = (ull*)sm;                  // [gate][kp][q]
    float* xsf  = sm + 24576;                // [bb][k], row stride 388 (float4-aligned)
    float* hc   = sm + 49408;                // 4*512
    float* z1s  = sm + 51456;                // 4*128
    float* es   = sm + 51968;                // 4*128
    float* w3s  = sm + 52480;                // 128
    float* b1s  = sm + 52608;                // 128

    int bid = blockIdx.x, tid = threadIdx.x;
    int wrp = tid >> 5, l = tid & 31;
    int grp = bid >> 4, u = bid & 15;
    int jt  = u, bt = grp;
    int b0  = grp*64 + u*4;                  // attention batches

    // stage LSTM weight slice into smem once (k-paired per gate)
    for (int idx = tid; idx < 192*16; idx += NTHR) {
        int kp = idx >> 4, q2 = idx & 15;
        int j  = jt*16 + q2;
        float4 w0 = g_Wt4[(2*kp  )*256 + j];
        float4 w1 = g_Wt4[(2*kp+1)*256 + j];
        wsmu[(0*192 + kp)*16 + q2] = pack2(w0.x, w1.x);
        wsmu[(1*192 + kp)*16 + q2] = pack2(w0.y, w1.y);
        wsmu[(2*192 + kp)*16 + q2] = pack2(w0.z, w1.z);
        wsmu[(3*192 + kp)*16 + q2] = pack2(w0.w, w1.w);
    }
    // step-invariant small arrays
    for (int i = tid; i < 128; i += NTHR) {
        w3s[i] = (i < TM1) ? W3[i] : 0.0f;
        b1s[i] = (i < TM1) ? b1[i] : 0.0f;
    }
    float b3v = b3[0];

    // GEMM mapping: q = hidden unit, bg = 4-batch group, kh = k-half
    int q  = tid & 15, bg = (tid >> 4) & 15, kh = tid >> 8;
    int jj = jt*16 + q;
    float bI = g_bias[jj], bF = g_bias[256+jj], bG = g_bias[512+jj], bO = g_bias[768+jj];
    float creg[4] = {0.f, 0.f, 0.f, 0.f};    // live in kh==0 threads

    // attention per-thread ids
    int sA  = tid & 127, kq = tid >> 7;      // stage-1: s-lane, k-quarter
    int biB = tid >> 7,  nB = tid & 127;     // stage-2: (bi, n) one per thread
    __syncthreads();

    unsigned bar = 0;
    for (int t = 0; t < TM1; t++) {
        const float* hsrc = g_h[t & 1];
        const float* csrc = g_c[t & 1];

        // ============ ATTENTION (batches b0..b0+3) ============
        {
            // stage hc: 1 float4 per thread
            {
                int bi = tid >> 7, j4 = tid & 127;
                float4 v = (j4 < 64)
                    ? ((const float4*)(hsrc + (b0+bi)*HH))[j4]
                    : ((const float4*)(csrc + (b0+bi)*HH))[j4-64];
                ((float4*)hc)[tid] = v;
            }
            __syncthreads();

            // stage 1: per-thread partial dot over k-quarter, FFMA2
            {
                const ull* wp  = g_W1T2 + (size_t)(kq*64)*128 + sA;  // row stride 128 ull
                const ull* hcu = (const ull*)hc;                      // [bi][256]
                ull a0=0, a1=0, a2=0, a3=0;
                int kbase = kq*64;
                #pragma unroll 4
                for (int kk = 0; kk < 64; kk++) {
                    ull wv = wp[kk*128];
                    ull h0 = hcu[0*256 + kbase + kk];
                    ull h1 = hcu[1*256 + kbase + kk];
                    ull h2 = hcu[2*256 + kbase + kk];
                    ull h3 = hcu[3*256 + kbase + kk];
                    FFMA2(a0, wv, h0); FFMA2(a1, wv, h1);
                    FFMA2(a2, wv, h2); FFMA2(a3, wv, h3);
                }
                float* z1p = xsf;            // [kq][bi][128] partials
                float2 p;
                p = unpack2(a0); z1p[(kq*4+0)*128 + sA] = p.x + p.y;
                p = unpack2(a1); z1p[(kq*4+1)*128 + sA] = p.x + p.y;
                p = unpack2(a2); z1p[(kq*4+2)*128 + sA] = p.x + p.y;
                p = unpack2(a3); z1p[(kq*4+3)*128 + sA] = p.x + p.y;
            }
            __syncthreads();
            {   // combine partials -> z1s
                const float* z1p = xsf;
                int bi = tid >> 7, ss = tid & 127;
                float z = z1p[(0*4+bi)*128+ss] + z1p[(1*4+bi)*128+ss]
                        + z1p[(2*4+bi)*128+ss] + z1p[(3*4+bi)*128+ss];
                z1s[bi*128 + ss] = z + b1s[ss];
            }
            __syncthreads();

            // stage 2: one (bi, n) per thread; coalesced z2T, no shuffles
            {
                const float* zrow = g_z2T + (size_t)(b0+biB)*TM1*NF + nB;
                const float* z1r  = z1s + biB*128;
                float acc = 0.0f;
                #pragma unroll 3
                for (int s = 0; s < TM1; s++)
                    acc = fmaf(w3s[s], tanha(z1r[s] + zrow[(size_t)s*NF]), acc);
                es[biB*128 + nB] = acc + b3v;
            }
            __syncthreads();

            // softmax over n, write w = attn * x_t
            if (wrp < 4) {
                int bi = wrp, b = b0 + bi;
                float v0 = es[bi*128 + l],      v1 = es[bi*128 + 32 + l];
                float v2 = es[bi*128 + 64 + l], v3 = es[bi*128 + 96 + l];
                float m = wmax(fmaxf(fmaxf(v0, v1), fmaxf(v2, v3)));
                float e0 = ex2f((v0 - m) * 1.4426950408889634f);
                float e1 = ex2f((v1 - m) * 1.4426950408889634f);
                float e2 = ex2f((v2 - m) * 1.4426950408889634f);
                float e3 = ex2f((v3 - m) * 1.4426950408889634f);
                float r = rcpf(wsum(e0 + e1 + e2 + e3));
                const float* xrow = in  + (size_t)b*TM1*NF + t*NF;
                float*       orow = out + (size_t)b*TM1*NF + t*NF;
                orow[l     ] = e0 * r * xrow[l     ];
                orow[l + 32] = e1 * r * xrow[l + 32];
                orow[l + 64] = e2 * r * xrow[l + 64];
                orow[l + 96] = e3 * r * xrow[l + 96];
            }
        }
        groupbar(grp, ++bar);   // w(t) visible within group; h/c reads done

        // ============ LSTM GEMM + cell (64 batches x 16 j, k split in 2) ====
        {
            // stage x: float4 loads (w from out, h from hsrc)
            for (int i = tid; i < 64*96; i += NTHR) {
                int bb = i / 96, k4 = i - bb*96;
                int b  = bt*64 + bb;
                float4 v = (k4 < 32)
                    ? *(const float4*)(out + (size_t)b*TM1*NF + t*NF + k4*4)
                    : *(const float4*)(hsrc + b*HH + (k4-32)*4);
                *(float4*)&xsf[bb*388 + k4*4] = v;
            }
            __syncthreads();

            const ull* xu = (const ull*)xsf;   // row stride 194 ull
            const ull* x0 = xu + (bg*4 + 0)*194 + kh*96;
            const ull* x1 = xu + (bg*4 + 1)*194 + kh*96;
            const ull* x2 = xu + (bg*4 + 2)*194 + kh*96;
            const ull* x3 = xu + (bg*4 + 3)*194 + kh*96;
            const ull* wI = wsmu + (0*192 + kh*96)*16 + q;
            const ull* wF = wsmu + (1*192 + kh*96)*16 + q;
            const ull* wG = wsmu + (2*192 + kh*96)*16 + q;
            const ull* wO = wsmu + (3*192 + kh*96)*16 + q;

            ull aI[4] = {0,0,0,0}, aF[4] = {0,0,0,0}, aG[4] = {0,0,0,0}, aO[4] = {0,0,0,0};

            #pragma unroll 2
            for (int kp = 0; kp < 96; kp++) {
                ull vI = wI[kp*16], vF = wF[kp*16], vG = wG[kp*16], vO = wO[kp*16];
                ull xv0 = x0[kp], xv1 = x1[kp], xv2 = x2[kp], xv3 = x3[kp];
                FFMA2(aI[0], vI, xv0); FFMA2(aI[1], vI, xv1); FFMA2(aI[2], vI, xv2); FFMA2(aI[3], vI, xv3);
                FFMA2(aF[0], vF, xv0); FFMA2(aF[1], vF, xv1); FFMA2(aF[2], vF, xv2); FFMA2(aF[3], vF, xv3);
                FFMA2(aG[0], vG, xv0); FFMA2(aG[1], vG, xv1); FFMA2(aG[2], vG, xv2); FFMA2(aG[3], vG, xv3);
                FFMA2(aO[0], vO, xv0); FFMA2(aO[1], vO, xv1); FFMA2(aO[2], vO, xv2); FFMA2(aO[3], vO, xv3);
            }

            // combine k-halves via smem scratch (reuse xsf region)
            __syncthreads();
            ull* scratch = (ull*)xsf;
            if (kh == 1) {
                ull* d = scratch + (size_t)(bg*16 + q)*16;
                d[0]  = aI[0]; d[1]  = aI[1]; d[2]  = aI[2]; d[3]  = aI[3];
                d[4]  = aF[0]; d[5]  = aF[1]; d[6]  = aF[2]; d[7]  = aF[3];
                d[8]  = aG[0]; d[9]  = aG[1]; d[10] = aG[2]; d[11] = aG[3];
                d[12] = aO[0]; d[13] = aO[1]; d[14] = aO[2]; d[15] = aO[3];
            }
            __syncthreads();

            if (kh == 0) {
                const ull* d = scratch + (size_t)(bg*16 + q)*16;
                float* cdst = g_c[(t + 1) & 1];
                float* hdst = g_h[(t + 1) & 1];
                #pragma unroll
                for (int m = 0; m < 4; m++) {
                    float2 pI = unpack2(aI[m]), rI = unpack2(d[m]);
                    float2 pF = unpack2(aF[m]), rF = unpack2(d[4+m]);
                    float2 pG = unpack2(aG[m]), rG = unpack2(d[8+m]);
                    float2 pO = unpack2(aO[m]), rO = unpack2(d[12+m]);
                    float gi = (pI.x + pI.y) + (rI.x + rI.y) + bI;
                    float gf = (pF.x + pF.y) + (rF.x + rF.y) + bF;
                    float gg = (pG.x + pG.y) + (rG.x + rG.y) + bG;
                    float go = (pO.x + pO.y) + (rO.x + rO.y) + bO;
                    float iv = sigm_f(gi);
                    float fv = sigm_f(gf);
                    float gv = tanh_f(gg);
                    float ov = sigm_f(go);
                    float cn = fmaf(fv, creg[m], iv * gv);
                    creg[m] = cn;
                    float hn = ov * tanh_f(cn);
                    int b = bt*64 + bg*4 + m;
                    cdst[b*HH + jj] = cn;
                    hdst[b*HH + jj] = hn;
                    out[WOFF + (size_t)b*TM1*HH + t*HH + jj] = hn;
                }
            }
        }
        groupbar(grp, ++bar);   // h/c(t+1) visible within group
    }
}

// ---------------- launch ----------------
extern "C" void kernel_launch(void* const* d_in, const int* in_sizes, int n_in,
                              void* d_out, int out_size)
{
    const float* in   = (const float*)d_in[0];
    const float* W1   = (const float*)d_in[1];
    const float* b1   = (const float*)d_in[2];
    const float* W2   = (const float*)d_in[3];
    const float* b2   = (const float*)d_in[4];
    const float* W3   = (const float*)d_in[5];
    const float* b3   = (const float*)d_in[6];
    const float* W_ih = (const float*)d_in[7];
    const float* W_hh = (const float*)d_in[8];
    const float* b_ih = (const float*)d_in[9];
    const float* b_hh = (const float*)d_in[10];
    float* out = (float*)d_out;

    cudaFuncSetAttribute(persist_kernel, cudaFuncAttributeMaxDynamicSharedMemorySize, SMEM_PERSIST);

    prep_kernel<<<148, 256>>>(W_ih, W_hh, b_ih, b_hh, W2, W1);
    z2_kernel<<<1024, 256>>>(in, b2);
    persist_kernel<<<NBLK, NTHR, SMEM_PERSIST>>>(in, b1, W3, b3, out);
}